// round 2
// baseline (speedup 1.0000x reference)
#include <cuda_runtime.h>
#include <math.h>

// Scratch for batch-independent precomputation:
// [0..8] M1, [9..17] M2, [18] alpha, [19] beta, [20..22] const vec c
__device__ float g_prep[24];

__global__ void prep_kernel(const float* __restrict__ t,
                            const float* __restrict__ R,
                            const float* __restrict__ m,
                            const float* __restrict__ Wl1, const float* __restrict__ Wd1,
                            const float* __restrict__ Wl2, const float* __restrict__ Wd2,
                            const float* __restrict__ Wl3, const float* __restrict__ Wd3,
                            const float* __restrict__ Wl4, const float* __restrict__ Wd4,
                            const float* __restrict__ Wb1_lin,
                            const float* __restrict__ Wb1_d1, const float* __restrict__ Wb1_d2,
                            const float* __restrict__ Wb2_lin,
                            const float* __restrict__ Wb2_d1, const float* __restrict__ Wb2_d2,
                            const float* __restrict__ Wout)
{
    const int lane = threadIdx.x;            // single warp (32 threads)
    __shared__ float mm[20][3];              // mm[f][k] = (R@m)[k][f]
    __shared__ float sM[4][9];               // M1..M4

    // mm = (R @ m)^T  (60 entries, cooperative)
    for (int idx = lane; idx < 60; idx += 32) {
        int f = idx / 3, k = idx % 3;
        float s = 0.f;
        #pragma unroll
        for (int j = 0; j < 3; ++j) s += R[k * 3 + j] * m[j * 20 + f];
        mm[f][k] = s;
    }
    __syncwarp();

    // Threads 0..3 each compute one map_m -> M_i = out^T out
    if (lane < 4) {
        const float* Wl = (lane == 0) ? Wl1 : (lane == 1) ? Wl2 : (lane == 2) ? Wl3 : Wl4;
        const float* Wd = (lane == 0) ? Wd1 : (lane == 1) ? Wd2 : (lane == 2) ? Wd3 : Wd4;
        float y[3][3], d[3][3], o[3][3];
        #pragma unroll
        for (int oo = 0; oo < 3; ++oo)
            #pragma unroll
            for (int k = 0; k < 3; ++k) {
                float s = 0.f;
                for (int f = 0; f < 20; ++f) s += Wl[oo * 20 + f] * mm[f][k];
                y[oo][k] = s;
            }
        #pragma unroll
        for (int oo = 0; oo < 3; ++oo)
            #pragma unroll
            for (int k = 0; k < 3; ++k) {
                float s = 0.f;
                #pragma unroll
                for (int f = 0; f < 3; ++f) s += Wd[oo * 3 + f] * y[f][k];
                d[oo][k] = s;
            }
        #pragma unroll
        for (int oo = 0; oo < 3; ++oo) {
            float kxd = -2.f * (y[oo][0] * d[oo][0] + y[oo][1] * d[oo][1] + y[oo][2] * d[oo][2]);
            float kdd = -2.f * (d[oo][0] * d[oo][0] + d[oo][1] * d[oo][1] + d[oo][2] * d[oo][2]);
            float denom = fminf(kdd, -1e-12f);
            float fac = (kxd < 0.f) ? 0.f : (kxd / denom);
            #pragma unroll
            for (int k = 0; k < 3; ++k) o[oo][k] = y[oo][k] - fac * d[oo][k];
        }
        #pragma unroll
        for (int p = 0; p < 3; ++p)
            #pragma unroll
            for (int q = 0; q < 3; ++q)
                sM[lane][p * 3 + q] =
                    o[0][p] * o[0][q] + o[1][p] * o[1][q] + o[2][p] * o[2][q];
    }
    __syncwarp();

    // Per-channel contractions: lane f handles channel f (f < 20)
    float pa = 0.f, pb = 0.f, pau = 0.f, pbu = 0.f;
    if (lane < 20) {
        float c1 = 0.f, c2 = 0.f, c1u = 0.f, c2u = 0.f;
        for (int q = 0; q < 20; ++q) {
            float b1 = Wb1_lin[q], b2 = Wb2_lin[q];
            c1  += Wb1_d1[lane * 20 + q] * b1;
            c2  += Wb1_d2[lane * 20 + q] * b1;
            c1u += Wb2_d1[lane * 20 + q] * b2;
            c2u += Wb2_d2[lane * 20 + q] * b2;
        }
        float wo = Wout[lane];
        pa  = wo * c1 * c2;
        pb  = wo * Wb1_lin[lane];
        pau = wo * c1u * c2u;
        pbu = wo * Wb2_lin[lane];
    }
    #pragma unroll
    for (int off = 16; off; off >>= 1) {
        pa  += __shfl_down_sync(0xffffffffu, pa, off);
        pb  += __shfl_down_sync(0xffffffffu, pb, off);
        pau += __shfl_down_sync(0xffffffffu, pau, off);
        pbu += __shfl_down_sync(0xffffffffu, pbu, off);
    }

    if (lane == 0) {
        float tv = t[0];
        float sv = sinf(tv), cv = cosf(tv);
        float u0[3] = {10.f * sv, 10.f * cv, 10.f * sv};
        float u[3];
        #pragma unroll
        for (int k = 0; k < 3; ++k)
            u[k] = R[k * 3 + 0] * u0[0] + R[k * 3 + 1] * u0[1] + R[k * 3 + 2] * u0[2];
        float w1[3], w2[3];
        #pragma unroll
        for (int p = 0; p < 3; ++p) {
            w1[p] = sM[2][p * 3 + 0] * u[0] + sM[2][p * 3 + 1] * u[1] + sM[2][p * 3 + 2] * u[2];
            w2[p] = sM[3][p * 3 + 0] * u[0] + sM[3][p * 3 + 1] * u[1] + sM[3][p * 3 + 2] * u[2];
        }
        float cu[3] = {w1[1] * w2[2] - w1[2] * w2[1],
                       w1[2] * w2[0] - w1[0] * w2[2],
                       w1[0] * w2[1] - w1[1] * w2[0]};
        #pragma unroll
        for (int i = 0; i < 9; ++i) { g_prep[i] = sM[0][i]; g_prep[9 + i] = sM[1][i]; }
        g_prep[18] = pa;
        g_prep[19] = pb;
        #pragma unroll
        for (int k = 0; k < 3; ++k) g_prep[20 + k] = pau * cu[k] + pbu * u[k];
    }
}

// out_b = alpha * cross(M1 x_b, M2 x_b) + beta * x_b + c
// 4 states per thread => 3x float4 loads + 3x float4 stores per thread.
__global__ void main_kernel(const float* __restrict__ x, float* __restrict__ out, int nquad)
{
    int i = blockIdx.x * blockDim.x + threadIdx.x;
    if (i >= nquad) return;

    float M1[9], M2[9];
    #pragma unroll
    for (int j = 0; j < 9; ++j) { M1[j] = g_prep[j]; M2[j] = g_prep[9 + j]; }
    const float al = g_prep[18], be = g_prep[19];
    const float c0 = g_prep[20], c1 = g_prep[21], c2 = g_prep[22];

    const float4* __restrict__ x4 = (const float4*)x;
    float4* __restrict__ o4 = (float4*)out;

    float4 a = x4[3 * i + 0];
    float4 b = x4[3 * i + 1];
    float4 c = x4[3 * i + 2];
    float xs[12] = {a.x, a.y, a.z, a.w, b.x, b.y, b.z, b.w, c.x, c.y, c.z, c.w};
    float os[12];

    #pragma unroll
    for (int s = 0; s < 4; ++s) {
        float px = xs[3 * s + 0], py = xs[3 * s + 1], pz = xs[3 * s + 2];
        float y0 = M1[0] * px + M1[1] * py + M1[2] * pz;
        float y1 = M1[3] * px + M1[4] * py + M1[5] * pz;
        float y2 = M1[6] * px + M1[7] * py + M1[8] * pz;
        float z0 = M2[0] * px + M2[1] * py + M2[2] * pz;
        float z1 = M2[3] * px + M2[4] * py + M2[5] * pz;
        float z2 = M2[6] * px + M2[7] * py + M2[8] * pz;
        float r0 = y1 * z2 - y2 * z1;
        float r1 = y2 * z0 - y0 * z2;
        float r2 = y0 * z1 - y1 * z0;
        os[3 * s + 0] = al * r0 + be * px + c0;
        os[3 * s + 1] = al * r1 + be * py + c1;
        os[3 * s + 2] = al * r2 + be * pz + c2;
    }

    o4[3 * i + 0] = make_float4(os[0], os[1], os[2], os[3]);
    o4[3 * i + 1] = make_float4(os[4], os[5], os[6], os[7]);
    o4[3 * i + 2] = make_float4(os[8], os[9], os[10], os[11]);
}

// Scalar tail (nstates not divisible by 4) — not hit for B=1e6 but kept for safety.
__global__ void tail_kernel(const float* __restrict__ x, float* __restrict__ out,
                            int start, int nstates)
{
    int s = start + blockIdx.x * blockDim.x + threadIdx.x;
    if (s >= nstates) return;
    float M1[9], M2[9];
    #pragma unroll
    for (int j = 0; j < 9; ++j) { M1[j] = g_prep[j]; M2[j] = g_prep[9 + j]; }
    const float al = g_prep[18], be = g_prep[19];
    float px = x[3 * s], py = x[3 * s + 1], pz = x[3 * s + 2];
    float y0 = M1[0] * px + M1[1] * py + M1[2] * pz;
    float y1 = M1[3] * px + M1[4] * py + M1[5] * pz;
    float y2 = M1[6] * px + M1[7] * py + M1[8] * pz;
    float z0 = M2[0] * px + M2[1] * py + M2[2] * pz;
    float z1 = M2[3] * px + M2[4] * py + M2[5] * pz;
    float z2 = M2[6] * px + M2[7] * py + M2[8] * pz;
    out[3 * s + 0] = al * (y1 * z2 - y2 * z1) + be * px + g_prep[20];
    out[3 * s + 1] = al * (y2 * z0 - y0 * z2) + be * py + g_prep[21];
    out[3 * s + 2] = al * (y0 * z1 - y1 * z0) + be * pz + g_prep[22];
}

extern "C" void kernel_launch(void* const* d_in, const int* in_sizes, int n_in,
                              void* d_out, int out_size)
{
    const float* t       = (const float*)d_in[0];
    const float* x       = (const float*)d_in[1];
    const float* R       = (const float*)d_in[2];
    const float* m       = (const float*)d_in[3];
    const float* Wl1     = (const float*)d_in[4];
    const float* Wd1     = (const float*)d_in[5];
    const float* Wl2     = (const float*)d_in[6];
    const float* Wd2     = (const float*)d_in[7];
    const float* Wl3     = (const float*)d_in[8];
    const float* Wd3     = (const float*)d_in[9];
    const float* Wl4     = (const float*)d_in[10];
    const float* Wd4     = (const float*)d_in[11];
    const float* Wb1_lin = (const float*)d_in[12];
    const float* Wb1_d1  = (const float*)d_in[13];
    const float* Wb1_d2  = (const float*)d_in[14];
    const float* Wb2_lin = (const float*)d_in[15];
    const float* Wb2_d1  = (const float*)d_in[16];
    const float* Wb2_d2  = (const float*)d_in[17];
    const float* Wout    = (const float*)d_in[18];
    float* out = (float*)d_out;

    const int nstates = in_sizes[1] / 3;
    const int nquad   = nstates / 4;
    const int tail    = nstates - nquad * 4;

    prep_kernel<<<1, 32>>>(t, R, m, Wl1, Wd1, Wl2, Wd2, Wl3, Wd3, Wl4, Wd4,
                           Wb1_lin, Wb1_d1, Wb1_d2, Wb2_lin, Wb2_d1, Wb2_d2, Wout);

    if (nquad > 0) {
        const int threads = 256;
        const int blocks = (nquad + threads - 1) / threads;
        main_kernel<<<blocks, threads>>>(x, out, nquad);
    }
    if (tail > 0) {
        tail_kernel<<<1, 32>>>(x, out, nquad * 4, nstates);
    }
}